// round 15
// baseline (speedup 1.0000x reference)
#include <cuda_runtime.h>
#include <cuda_fp16.h>
#include <cstdint>

// ---------------------------------------------------------------------------
// Problem constants
// ---------------------------------------------------------------------------
#define BB 32
#define DD 64
#define TT 2048
#define KK 1024
#define NN (BB * TT)              // 65536 rows
#define QELEMS (BB * DD * TT)     // 4194304
// Output (float32): [loss(1) | quantized(QELEMS) | indices(NN) | n_resurrected(1)]

#define TILE_M  256               // rows per CTA (32 per warp)
#define CHUNK_N 128               // codewords per staged chunk
#define GRID_M  (NN / TILE_M)     // 256 CTAs
#define NCHUNK  (KK / CHUNK_N)    // 8

#define B_BUF_BYTES 18432         // 128 rows x 144 B

// Dynamic smem layout (bytes)
#define SM_X     0                // 256 x 64 floats (xor-swizzled) = 65536
#define SM_B     65536            // 2 x 18432 = 36864 (cp.async ping-pong)
#define SM_CAND  102400           // 256 x 2 ints = 2048
#define SM_RED   104448           // 264 floats   = 1056
#define SM_TOTAL 105536

// Selection bias: cosines are in [-1.001, 1.001]; starting the MMA
// accumulator at +1.03125 keeps every dot strictly positive, so the raw
// float bit pattern is unsigned-monotone and keys need no per-value FADD.
#define ACC_BIAS 1.03125f

__device__ __half g_wh[KK * DD];     // normalized codebook, fp16 (mma operand)
__device__ float  g_wnorm[KK * DD];  // normalized codebook, fp32 (exact rescore)
__device__ float  g_partial[GRID_M];
__device__ int    g_ctr;             // zero-initialized; reset by last block

// m16n8k16 fp16 MMA, fp32 accum, D += A*B
#define MMA_F16(d, a, b0, b1)                                                 \
    asm volatile("mma.sync.aligned.m16n8k16.row.col.f32.f16.f16.f32 "         \
                 "{%0,%1,%2,%3}, {%4,%5,%6,%7}, {%8,%9}, {%0,%1,%2,%3};"      \
                 : "+f"((d)[0]), "+f"((d)[1]), "+f"((d)[2]), "+f"((d)[3])     \
                 : "r"((a)[0]), "r"((a)[1]), "r"((a)[2]), "r"((a)[3]),        \
                   "r"(b0), "r"(b1))

#define LDSM4(r, a)                                                           \
    asm volatile("ldmatrix.sync.aligned.m8n8.x4.shared.b16 {%0,%1,%2,%3}, [%4];" \
                 : "=r"((r)[0]), "=r"((r)[1]), "=r"((r)[2]), "=r"((r)[3])     \
                 : "r"(a))

// .cg: L2-only path, no L1 allocation (16B transfers)
#define CP_ASYNC_16(dst_u32, src_ptr) \
    asm volatile("cp.async.cg.shared.global [%0], [%1], 16;" \
                 :: "r"(dst_u32), "l"(src_ptr) : "memory")
#define CP_ASYNC_COMMIT() asm volatile("cp.async.commit_group;" ::: "memory")
#define CP_ASYNC_WAIT(n)  asm volatile("cp.async.wait_group %0;" :: "n"(n) : "memory")

__device__ __forceinline__ uint32_t smem_to_u32(const void* p) {
    uint32_t a;
    asm("{ .reg .u64 t; cvta.to.shared.u64 t, %1; cvt.u32.u64 %0, t; }" : "=r"(a) : "l"(p));
    return a;
}
__device__ __forceinline__ uint32_t pack_h2(float a, float b) {
    __half2 h = __floats2half2_rn(a, b);
    return *(uint32_t*)&h;
}

// ---------------------------------------------------------------------------
// Pre-kernel: normalize codebook -> fp16 operand + fp32 exact copy.
// One THREAD per row (16 LDG.128, MLP~16, no shuffles): latency-optimal
// shape for this tiny 640KB-traffic kernel.
// ---------------------------------------------------------------------------
__global__ __launch_bounds__(128)
void norm_weight_kernel(const float* __restrict__ w) {
    int row = blockIdx.x * 128 + threadIdx.x;    // grid 8 x 128 = 1024 rows
    const float4* src = (const float4*)(w + (size_t)row * DD);
    float4 v[16];
    #pragma unroll
    for (int i = 0; i < 16; ++i) v[i] = src[i];
    float ss = 0.0f;
    #pragma unroll
    for (int i = 0; i < 16; ++i)
        ss += v[i].x * v[i].x + v[i].y * v[i].y + v[i].z * v[i].z + v[i].w * v[i].w;
    float inv = 1.0f / fmaxf(sqrtf(ss), 1e-12f);

    float4* dstf = (float4*)(g_wnorm + (size_t)row * DD);
    uint32_t ph[32];
    #pragma unroll
    for (int i = 0; i < 16; ++i) {
        float4 nv = make_float4(v[i].x * inv, v[i].y * inv, v[i].z * inv, v[i].w * inv);
        dstf[i] = nv;
        ph[2 * i]     = pack_h2(nv.x, nv.y);
        ph[2 * i + 1] = pack_h2(nv.z, nv.w);
    }
    uint4* dsth = (uint4*)(g_wh + (size_t)row * DD);
    #pragma unroll
    for (int i = 0; i < 8; ++i)
        dsth[i] = make_uint4(ph[4 * i], ph[4 * i + 1], ph[4 * i + 2], ph[4 * i + 3]);
}

// ---------------------------------------------------------------------------
// Main fused kernel
//
// Synchronization note: sX/sCand/sRED rows are WARP-PRIVATE (row r is
// written by thread r and only read by warp r/32) -> __syncwarp suffices
// everywhere except (a) the staged B chunks, which all threads cooperatively
// fill via cp.async (one __syncthreads per chunk), and (b) the final
// cross-warp loss reduction.
// ---------------------------------------------------------------------------
__global__ __launch_bounds__(256, 2)
void vq_all_kernel(const float* __restrict__ in, float* __restrict__ out,
                   int out_size) {
    extern __shared__ char smem[];
    float*    sX    = (float*)(smem + SM_X);
    __half*   sB    = (__half*)(smem + SM_B);
    int*      sCand = (int*)(smem + SM_CAND);
    float*    sRED  = (float*)(smem + SM_RED);
    __shared__ int sLast;

    const int tid  = threadIdx.x;
    const int wid  = tid >> 5;
    const int lane = tid & 31;
    const int g    = lane >> 2;   // groupID (0..7)
    const int tig  = lane & 3;    // thread in group
    const int lr   = lane & 7;    // ldmatrix row
    const int lj   = lane >> 3;   // ldmatrix tile

    const uint32_t sB_u32 = smem_to_u32(sB);

    // ---- Prologue: stage chunk 0 via cp.async (overlaps phase 1) ----
    {
        const char* src = (const char*)g_wh;
        #pragma unroll
        for (int it = 0; it < 4; ++it) {
            int gi  = tid + it * 256;          // [0,1024) 16B units
            int row = gi >> 3;
            int j   = gi & 7;
            CP_ASYNC_16(sB_u32 + (uint32_t)(row * 144 + j * 16), src + gi * 16);
        }
        CP_ASYNC_COMMIT();
    }

    // ---- Phase 1: load + normalize 256 rows into xor-swizzled smem X ----
    {
        int n = blockIdx.x * TILE_M + tid;
        int b = n >> 11;
        int t = n & (TT - 1);
        const float* xp = in + (size_t)b * DD * TT + t;
        float x[DD];
        float ss = 0.0f;
        #pragma unroll
        for (int d = 0; d < DD; ++d) { float v = xp[(size_t)d * TT]; x[d] = v; ss += v * v; }
        float inv = 1.0f / fmaxf(sqrtf(ss), 1e-12f);
        const int sw = tid & 15;
        #pragma unroll
        for (int cd = 0; cd < 16; ++cd) {
            *(float4*)(sX + tid * 64 + ((cd ^ sw) << 2)) =
                make_float4(x[4 * cd] * inv, x[4 * cd + 1] * inv,
                            x[4 * cd + 2] * inv, x[4 * cd + 3] * inv);
        }
    }
    __syncwarp();   // sX rows are warp-private: only this warp reads them

    // ---- Resident A fragments (fp16) for this warp's 32 rows (2 groups) ----
    const int rbase = wid * 32;
    uint32_t A[2][4][4];
    #pragma unroll
    for (int grp = 0; grp < 2; ++grp) {
        const int r0 = rbase + grp * 16 + g;
        const int r1 = r0 + 8;
        const int s0 = r0 & 15, s1 = r1 & 15;
        #pragma unroll
        for (int c = 0; c < 4; ++c) {
            const int ch0 = c * 4 + (tig >> 1);        // chunk of k0 = 16c + 2tig
            const int off = (2 * tig) & 3;
            const float* pa  = sX + r0 * 64 + ((ch0 ^ s0) << 2) + off;
            const float* pb  = sX + r1 * 64 + ((ch0 ^ s1) << 2) + off;
            const float* pa8 = sX + r0 * 64 + (((ch0 + 2) ^ s0) << 2) + off;
            const float* pb8 = sX + r1 * 64 + (((ch0 + 2) ^ s1) << 2) + off;
            A[grp][c][0] = pack_h2(pa[0],  pa[1]);
            A[grp][c][1] = pack_h2(pb[0],  pb[1]);
            A[grp][c][2] = pack_h2(pa8[0], pa8[1]);
            A[grp][c][3] = pack_h2(pb8[0], pb8[1]);
        }
    }

    uint32_t k0[4] = {0, 0, 0, 0}, k1[4] = {0, 0, 0, 0};   // packed top-2 keys
    const uint32_t ldsm_base = sB_u32 + (uint32_t)(lr * 144 + lj * 16);

    // ---- Mainloop: ONE block sync per chunk ----
    #pragma unroll 1
    for (int nt = 0; nt < NCHUNK; ++nt) {
        CP_ASYNC_WAIT(0);
        __syncthreads();

        if (nt < NCHUNK - 1) {
            const char* src = (const char*)(g_wh + (size_t)(nt + 1) * CHUNK_N * DD);
            uint32_t dstb = sB_u32 + (uint32_t)(((nt + 1) & 1) * B_BUF_BYTES);
            #pragma unroll
            for (int it = 0; it < 4; ++it) {
                int gi  = tid + it * 256;
                int row = gi >> 3;
                int j   = gi & 7;
                CP_ASYNC_16(dstb + (uint32_t)(row * 144 + j * 16), src + gi * 16);
            }
            CP_ASYNC_COMMIT();
        }

        const uint32_t lbase = ldsm_base + (uint32_t)((nt & 1) * B_BUF_BYTES);
        const uint32_t code_base = 1023u - (uint32_t)(nt * 64 + tig);

        // ---- 8 sub-tiles of 16 codewords ----
        #pragma unroll
        for (int pp = 0; pp < 8; ++pp) {
            const int n0 = pp * 16;
            uint32_t Bf[4][4];                       // [h*2+seg][tile]
            const uint32_t a0 = lbase + (uint32_t)(n0 * 144);
            LDSM4(Bf[0], a0);                        // h0, k 0..31
            LDSM4(Bf[1], a0 + 64);                   // h0, k 32..63
            LDSM4(Bf[2], a0 + 8 * 144);              // h1, k 0..31
            LDSM4(Bf[3], a0 + 8 * 144 + 64);         // h1, k 32..63

            float acc[2][2][4];
            #pragma unroll
            for (int grp = 0; grp < 2; ++grp)
                #pragma unroll
                for (int h = 0; h < 2; ++h)
                    #pragma unroll
                    for (int e = 0; e < 4; ++e) acc[grp][h][e] = ACC_BIAS;
            #pragma unroll
            for (int c = 0; c < 4; ++c) {
                const int bi_ = c >> 1;
                const int be  = (c & 1) * 2;
                MMA_F16(acc[0][0], A[0][c], Bf[bi_][be],     Bf[bi_][be + 1]);
                MMA_F16(acc[0][1], A[0][c], Bf[2 + bi_][be], Bf[2 + bi_][be + 1]);
                MMA_F16(acc[1][0], A[1][c], Bf[bi_][be],     Bf[bi_][be + 1]);
                MMA_F16(acc[1][1], A[1][c], Bf[2 + bi_][be], Bf[2 + bi_][be + 1]);
            }
            // pair-max -> packed key (bits pre-biased by ACC_BIAS) -> top-2
            #pragma unroll
            for (int grp = 0; grp < 2; ++grp) {
                #pragma unroll
                for (int h = 0; h < 2; ++h) {
                    const uint32_t code = code_base - (uint32_t)(pp * 8 + h * 4);
                    float vA = fmaxf(acc[grp][h][0], acc[grp][h][1]);
                    float vB = fmaxf(acc[grp][h][2], acc[grp][h][3]);
                    uint32_t kA = (__float_as_uint(vA) & 0xFFFFFC00u) | code;
                    uint32_t kB = (__float_as_uint(vB) & 0xFFFFFC00u) | code;
                    const int rY = grp * 2, rZ = rY + 1;
                    uint32_t tA = min(k0[rY], kA);
                    k0[rY] = max(k0[rY], kA);
                    k1[rY] = max(k1[rY], tA);
                    uint32_t tB = min(k0[rZ], kB);
                    k0[rZ] = max(k0[rZ], kB);
                    k1[rZ] = max(k1[rZ], tB);
                }
            }
        }
    }

    // ---- Merge top-2 key sets across the 4 lanes of each group ----
    #pragma unroll
    for (int r = 0; r < 4; ++r) {
        #pragma unroll
        for (int off = 1; off <= 2; off <<= 1) {
            uint32_t o0 = __shfl_xor_sync(0xFFFFFFFFu, k0[r], off);
            uint32_t o1 = __shfl_xor_sync(0xFFFFFFFFu, k1[r], off);
            uint32_t mn = min(k0[r], o0);
            k0[r] = max(k0[r], o0);
            k1[r] = max(max(k1[r], o1), mn);
        }
        if (tig == 0) {
            int row = rbase + (r >> 1) * 16 + (r & 1) * 8 + g;
            sCand[row * 2 + 0] = 1023 - (int)(k0[r] & 1023u);
            sCand[row * 2 + 1] = 1023 - (int)(k1[r] & 1023u);
        }
    }
    __syncwarp();   // sCand rows are warp-private

    // ---- Cooperative exact fp32 rescore (dot-only vs g_wnorm) ----
    // unroll 2: rows are independent; lets row s+1's candidate LDGs fly
    // under row s's shuffle-reduce chains.
    const float NEGINF = -3.402823466e+38f;
    #pragma unroll 2
    for (int s = 0; s < 4; ++s) {
        const int row = rbase + g * 4 + s;
        const int sw  = row & 15;
        const int p0 = sCand[row * 2], p1 = sCand[row * 2 + 1];
        int cand[4] = {2 * p0, 2 * p0 + 1, 2 * p1, 2 * p1 + 1};
        float4 xq[4];
        #pragma unroll
        for (int j = 0; j < 4; ++j)
            xq[j] = *(const float4*)(sX + row * 64 + (((tig * 4 + j) ^ sw) << 2));
        float best = NEGINF;
        int   bi   = KK;
        #pragma unroll
        for (int c = 0; c < 4; ++c) {
            const int idx = cand[c];
            const float4* wp = (const float4*)(g_wnorm + (size_t)idx * DD) + tig * 4;
            float dot = 0.0f;
            #pragma unroll
            for (int j = 0; j < 4; ++j) {
                float4 v = wp[j];
                dot += v.x * xq[j].x + v.y * xq[j].y + v.z * xq[j].z + v.w * xq[j].w;
            }
            dot += __shfl_xor_sync(0xFFFFFFFFu, dot, 1);
            dot += __shfl_xor_sync(0xFFFFFFFFu, dot, 2);
            if (dot > best || (dot == best && idx < bi)) { best = dot; bi = idx; }
        }
        // overwrite this row of sX with the (already normalized) winner
        {
            const float4* wp = (const float4*)(g_wnorm + (size_t)bi * DD) + tig * 4;
            #pragma unroll
            for (int j = 0; j < 4; ++j)
                *(float4*)(sX + row * 64 + (((tig * 4 + j) ^ sw) << 2)) = wp[j];
        }
        if (tig == 0) {
            sCand[row * 2] = bi;
            sRED[row] = 2.0f - 2.0f * best;   // ||q - x||^2 for unit vectors
        }
    }
    __syncwarp();   // sX winner rows + sCand/sRED are warp-private

    // ---- Winner phase: stream own smem row (now q) to gmem, coalesced ----
    {
        int n = blockIdx.x * TILE_M + tid;
        int b = n >> 11;
        int t = n & (TT - 1);
        const int sw = tid & 15;
        float* qp = out + 1 + (size_t)b * DD * TT + t;
        #pragma unroll
        for (int i = 0; i < 16; ++i) {
            float4 q = *(const float4*)(sX + tid * 64 + ((i ^ sw) << 2));
            qp[(size_t)(i * 4 + 0) * TT] = q.x;
            qp[(size_t)(i * 4 + 1) * TT] = q.y;
            qp[(size_t)(i * 4 + 2) * TT] = q.z;
            qp[(size_t)(i * 4 + 3) * TT] = q.w;
        }
        out[1 + QELEMS + n] = (float)sCand[tid * 2];
    }

    // ---- Block loss reduce: warp shuffles + one cross-warp step ----
    {
        float v = sRED[tid];
        #pragma unroll
        for (int o = 16; o; o >>= 1) v += __shfl_xor_sync(0xFFFFFFFFu, v, o);
        if (lane == 0) sRED[256 + wid] = v;
    }
    __syncthreads();
    if (wid == 0) {
        float v = (lane < 8) ? sRED[256 + lane] : 0.0f;
        #pragma unroll
        for (int o = 4; o; o >>= 1) v += __shfl_xor_sync(0xFFFFFFFFu, v, o);
        if (lane == 0) g_partial[blockIdx.x] = v;
    }

    // ---- Deterministic last-block loss finalize ----
    if (tid == 0) {
        __threadfence();
        int old = atomicAdd(&g_ctr, 1);
        sLast = (old == GRID_M - 1) ? 1 : 0;
    }
    __syncthreads();
    if (sLast) {
        float v = g_partial[tid];
        #pragma unroll
        for (int o = 16; o; o >>= 1) v += __shfl_xor_sync(0xFFFFFFFFu, v, o);
        if (lane == 0) sRED[256 + wid] = v;
        __syncthreads();
        if (tid == 0) {
            float s = 0.0f;
            #pragma unroll
            for (int i = 0; i < 8; ++i) s += sRED[256 + i];
            out[0] = 1.25f * s / (float)QELEMS;   // q_loss + 0.25*e_loss (equal in value)
            out[out_size - 1] = 0.0f;             // n_resurrected
            g_ctr = 0;                            // reset for next graph replay
        }
    }
}

// ---------------------------------------------------------------------------
extern "C" void kernel_launch(void* const* d_in, const int* in_sizes, int n_in,
                              void* d_out, int out_size) {
    const float* in = (const float*)d_in[0];   // [B, D, T] float32
    const float* w  = (const float*)d_in[1];   // [K, D]    float32
    float* out = (float*)d_out;

    cudaFuncSetAttribute(vq_all_kernel, cudaFuncAttributeMaxDynamicSharedMemorySize, SM_TOTAL);

    norm_weight_kernel<<<KK / 128, 128>>>(w);
    vq_all_kernel<<<GRID_M, 256, SM_TOTAL>>>(in, out, out_size);
}

// round 16
// speedup vs baseline: 1.0419x; 1.0419x over previous
#include <cuda_runtime.h>
#include <cuda_fp16.h>
#include <cstdint>

// ---------------------------------------------------------------------------
// Problem constants
// ---------------------------------------------------------------------------
#define BB 32
#define DD 64
#define TT 2048
#define KK 1024
#define NN (BB * TT)              // 65536 rows
#define QELEMS (BB * DD * TT)     // 4194304
// Output (float32): [loss(1) | quantized(QELEMS) | indices(NN) | n_resurrected(1)]

#define TILE_M  256               // rows per CTA (32 per warp)
#define CHUNK_N 128               // codewords per staged chunk
#define GRID_M  (NN / TILE_M)     // 256 CTAs
#define NCHUNK  (KK / CHUNK_N)    // 8

#define B_BUF_BYTES 18432         // 128 rows x 144 B

// Dynamic smem layout (bytes)
#define SM_X     0                // 256 x 64 floats (xor-swizzled) = 65536
#define SM_B     65536            // 2 x 18432 = 36864 (cp.async ping-pong)
#define SM_CAND  102400           // 256 x 2 ints = 2048
#define SM_RED   104448           // 264 floats   = 1056
#define SM_TOTAL 105536

// Selection bias: cosines are in [-1.001, 1.001]; starting the MMA
// accumulator at +1.03125 keeps every dot strictly positive, so the raw
// float bit pattern is unsigned-monotone and keys need no per-value FADD.
#define ACC_BIAS 1.03125f

__device__ __half g_wh[KK * DD];     // normalized codebook, fp16 (mma operand)
__device__ float  g_wnorm[KK * DD];  // normalized codebook, fp32 (exact rescore)
__device__ float  g_partial[GRID_M];
__device__ int    g_ctr;             // zero-initialized; reset by last block

// m16n8k16 fp16 MMA, fp32 accum, D += A*B
#define MMA_F16(d, a, b0, b1)                                                 \
    asm volatile("mma.sync.aligned.m16n8k16.row.col.f32.f16.f16.f32 "         \
                 "{%0,%1,%2,%3}, {%4,%5,%6,%7}, {%8,%9}, {%0,%1,%2,%3};"      \
                 : "+f"((d)[0]), "+f"((d)[1]), "+f"((d)[2]), "+f"((d)[3])     \
                 : "r"((a)[0]), "r"((a)[1]), "r"((a)[2]), "r"((a)[3]),        \
                   "r"(b0), "r"(b1))

#define LDSM4(r, a)                                                           \
    asm volatile("ldmatrix.sync.aligned.m8n8.x4.shared.b16 {%0,%1,%2,%3}, [%4];" \
                 : "=r"((r)[0]), "=r"((r)[1]), "=r"((r)[2]), "=r"((r)[3])     \
                 : "r"(a))

// .cg: L2-only path, no L1 allocation (16B transfers)
#define CP_ASYNC_16(dst_u32, src_ptr) \
    asm volatile("cp.async.cg.shared.global [%0], [%1], 16;" \
                 :: "r"(dst_u32), "l"(src_ptr) : "memory")
#define CP_ASYNC_COMMIT() asm volatile("cp.async.commit_group;" ::: "memory")
#define CP_ASYNC_WAIT(n)  asm volatile("cp.async.wait_group %0;" :: "n"(n) : "memory")

__device__ __forceinline__ uint32_t smem_to_u32(const void* p) {
    uint32_t a;
    asm("{ .reg .u64 t; cvta.to.shared.u64 t, %1; cvt.u32.u64 %0, t; }" : "=r"(a) : "l"(p));
    return a;
}
__device__ __forceinline__ uint32_t pack_h2(float a, float b) {
    __half2 h = __floats2half2_rn(a, b);
    return *(uint32_t*)&h;
}

// ---------------------------------------------------------------------------
// Pre-kernel: normalize codebook -> fp16 operand + fp32 exact copy.
// FOUR threads per row: 4x LDG.128 each (MLP 4), 2 butterfly shuffles in the
// 4-lane group, vectorized stores. 4096 threads / 16 CTAs — enough CTAs to
// hide DRAM latency (the R15 thread-per-row version had only 8 CTAs and
// regressed ~1.5us).
// ---------------------------------------------------------------------------
__global__ __launch_bounds__(256)
void norm_weight_kernel(const float* __restrict__ w) {
    int idx = blockIdx.x * 256 + threadIdx.x;    // 16 x 256 = 4096 = 1024 rows x 4
    int row = idx >> 2;
    int q   = idx & 3;                           // quarter of the row (16 floats)

    const float4* src = (const float4*)(w + (size_t)row * DD) + q * 4;
    float4 v[4];
    #pragma unroll
    for (int i = 0; i < 4; ++i) v[i] = src[i];

    float ss = 0.0f;
    #pragma unroll
    for (int i = 0; i < 4; ++i)
        ss += v[i].x * v[i].x + v[i].y * v[i].y + v[i].z * v[i].z + v[i].w * v[i].w;
    ss += __shfl_xor_sync(0xFFFFFFFFu, ss, 1);
    ss += __shfl_xor_sync(0xFFFFFFFFu, ss, 2);
    float inv = 1.0f / fmaxf(sqrtf(ss), 1e-12f);

    float4* dstf = (float4*)(g_wnorm + (size_t)row * DD) + q * 4;
    uint32_t ph[8];
    #pragma unroll
    for (int i = 0; i < 4; ++i) {
        float4 nv = make_float4(v[i].x * inv, v[i].y * inv, v[i].z * inv, v[i].w * inv);
        dstf[i] = nv;
        ph[2 * i]     = pack_h2(nv.x, nv.y);
        ph[2 * i + 1] = pack_h2(nv.z, nv.w);
    }
    uint4* dsth = (uint4*)(g_wh + (size_t)row * DD) + q * 2;
    dsth[0] = make_uint4(ph[0], ph[1], ph[2], ph[3]);
    dsth[1] = make_uint4(ph[4], ph[5], ph[6], ph[7]);
}

// ---------------------------------------------------------------------------
// Main fused kernel (identical to R15 — its ncu dur improved 55.3 -> 53.5)
//
// Synchronization note: sX/sCand/sRED rows are WARP-PRIVATE (row r is
// written by thread r and only read by warp r/32) -> __syncwarp suffices
// everywhere except (a) the staged B chunks, which all threads cooperatively
// fill via cp.async (one __syncthreads per chunk), and (b) the final
// cross-warp loss reduction.
// ---------------------------------------------------------------------------
__global__ __launch_bounds__(256, 2)
void vq_all_kernel(const float* __restrict__ in, float* __restrict__ out,
                   int out_size) {
    extern __shared__ char smem[];
    float*    sX    = (float*)(smem + SM_X);
    __half*   sB    = (__half*)(smem + SM_B);
    int*      sCand = (int*)(smem + SM_CAND);
    float*    sRED  = (float*)(smem + SM_RED);
    __shared__ int sLast;

    const int tid  = threadIdx.x;
    const int wid  = tid >> 5;
    const int lane = tid & 31;
    const int g    = lane >> 2;   // groupID (0..7)
    const int tig  = lane & 3;    // thread in group
    const int lr   = lane & 7;    // ldmatrix row
    const int lj   = lane >> 3;   // ldmatrix tile

    const uint32_t sB_u32 = smem_to_u32(sB);

    // ---- Prologue: stage chunk 0 via cp.async (overlaps phase 1) ----
    {
        const char* src = (const char*)g_wh;
        #pragma unroll
        for (int it = 0; it < 4; ++it) {
            int gi  = tid + it * 256;          // [0,1024) 16B units
            int row = gi >> 3;
            int j   = gi & 7;
            CP_ASYNC_16(sB_u32 + (uint32_t)(row * 144 + j * 16), src + gi * 16);
        }
        CP_ASYNC_COMMIT();
    }

    // ---- Phase 1: load + normalize 256 rows into xor-swizzled smem X ----
    {
        int n = blockIdx.x * TILE_M + tid;
        int b = n >> 11;
        int t = n & (TT - 1);
        const float* xp = in + (size_t)b * DD * TT + t;
        float x[DD];
        float ss = 0.0f;
        #pragma unroll
        for (int d = 0; d < DD; ++d) { float v = xp[(size_t)d * TT]; x[d] = v; ss += v * v; }
        float inv = 1.0f / fmaxf(sqrtf(ss), 1e-12f);
        const int sw = tid & 15;
        #pragma unroll
        for (int cd = 0; cd < 16; ++cd) {
            *(float4*)(sX + tid * 64 + ((cd ^ sw) << 2)) =
                make_float4(x[4 * cd] * inv, x[4 * cd + 1] * inv,
                            x[4 * cd + 2] * inv, x[4 * cd + 3] * inv);
        }
    }
    __syncwarp();   // sX rows are warp-private: only this warp reads them

    // ---- Resident A fragments (fp16) for this warp's 32 rows (2 groups) ----
    const int rbase = wid * 32;
    uint32_t A[2][4][4];
    #pragma unroll
    for (int grp = 0; grp < 2; ++grp) {
        const int r0 = rbase + grp * 16 + g;
        const int r1 = r0 + 8;
        const int s0 = r0 & 15, s1 = r1 & 15;
        #pragma unroll
        for (int c = 0; c < 4; ++c) {
            const int ch0 = c * 4 + (tig >> 1);        // chunk of k0 = 16c + 2tig
            const int off = (2 * tig) & 3;
            const float* pa  = sX + r0 * 64 + ((ch0 ^ s0) << 2) + off;
            const float* pb  = sX + r1 * 64 + ((ch0 ^ s1) << 2) + off;
            const float* pa8 = sX + r0 * 64 + (((ch0 + 2) ^ s0) << 2) + off;
            const float* pb8 = sX + r1 * 64 + (((ch0 + 2) ^ s1) << 2) + off;
            A[grp][c][0] = pack_h2(pa[0],  pa[1]);
            A[grp][c][1] = pack_h2(pb[0],  pb[1]);
            A[grp][c][2] = pack_h2(pa8[0], pa8[1]);
            A[grp][c][3] = pack_h2(pb8[0], pb8[1]);
        }
    }

    uint32_t k0[4] = {0, 0, 0, 0}, k1[4] = {0, 0, 0, 0};   // packed top-2 keys
    const uint32_t ldsm_base = sB_u32 + (uint32_t)(lr * 144 + lj * 16);

    // ---- Mainloop: ONE block sync per chunk ----
    #pragma unroll 1
    for (int nt = 0; nt < NCHUNK; ++nt) {
        CP_ASYNC_WAIT(0);
        __syncthreads();

        if (nt < NCHUNK - 1) {
            const char* src = (const char*)(g_wh + (size_t)(nt + 1) * CHUNK_N * DD);
            uint32_t dstb = sB_u32 + (uint32_t)(((nt + 1) & 1) * B_BUF_BYTES);
            #pragma unroll
            for (int it = 0; it < 4; ++it) {
                int gi  = tid + it * 256;
                int row = gi >> 3;
                int j   = gi & 7;
                CP_ASYNC_16(dstb + (uint32_t)(row * 144 + j * 16), src + gi * 16);
            }
            CP_ASYNC_COMMIT();
        }

        const uint32_t lbase = ldsm_base + (uint32_t)((nt & 1) * B_BUF_BYTES);
        const uint32_t code_base = 1023u - (uint32_t)(nt * 64 + tig);

        // ---- 8 sub-tiles of 16 codewords ----
        #pragma unroll
        for (int pp = 0; pp < 8; ++pp) {
            const int n0 = pp * 16;
            uint32_t Bf[4][4];                       // [h*2+seg][tile]
            const uint32_t a0 = lbase + (uint32_t)(n0 * 144);
            LDSM4(Bf[0], a0);                        // h0, k 0..31
            LDSM4(Bf[1], a0 + 64);                   // h0, k 32..63
            LDSM4(Bf[2], a0 + 8 * 144);              // h1, k 0..31
            LDSM4(Bf[3], a0 + 8 * 144 + 64);         // h1, k 32..63

            float acc[2][2][4];
            #pragma unroll
            for (int grp = 0; grp < 2; ++grp)
                #pragma unroll
                for (int h = 0; h < 2; ++h)
                    #pragma unroll
                    for (int e = 0; e < 4; ++e) acc[grp][h][e] = ACC_BIAS;
            #pragma unroll
            for (int c = 0; c < 4; ++c) {
                const int bi_ = c >> 1;
                const int be  = (c & 1) * 2;
                MMA_F16(acc[0][0], A[0][c], Bf[bi_][be],     Bf[bi_][be + 1]);
                MMA_F16(acc[0][1], A[0][c], Bf[2 + bi_][be], Bf[2 + bi_][be + 1]);
                MMA_F16(acc[1][0], A[1][c], Bf[bi_][be],     Bf[bi_][be + 1]);
                MMA_F16(acc[1][1], A[1][c], Bf[2 + bi_][be], Bf[2 + bi_][be + 1]);
            }
            // pair-max -> packed key (bits pre-biased by ACC_BIAS) -> top-2
            #pragma unroll
            for (int grp = 0; grp < 2; ++grp) {
                #pragma unroll
                for (int h = 0; h < 2; ++h) {
                    const uint32_t code = code_base - (uint32_t)(pp * 8 + h * 4);
                    float vA = fmaxf(acc[grp][h][0], acc[grp][h][1]);
                    float vB = fmaxf(acc[grp][h][2], acc[grp][h][3]);
                    uint32_t kA = (__float_as_uint(vA) & 0xFFFFFC00u) | code;
                    uint32_t kB = (__float_as_uint(vB) & 0xFFFFFC00u) | code;
                    const int rY = grp * 2, rZ = rY + 1;
                    uint32_t tA = min(k0[rY], kA);
                    k0[rY] = max(k0[rY], kA);
                    k1[rY] = max(k1[rY], tA);
                    uint32_t tB = min(k0[rZ], kB);
                    k0[rZ] = max(k0[rZ], kB);
                    k1[rZ] = max(k1[rZ], tB);
                }
            }
        }
    }

    // ---- Merge top-2 key sets across the 4 lanes of each group ----
    #pragma unroll
    for (int r = 0; r < 4; ++r) {
        #pragma unroll
        for (int off = 1; off <= 2; off <<= 1) {
            uint32_t o0 = __shfl_xor_sync(0xFFFFFFFFu, k0[r], off);
            uint32_t o1 = __shfl_xor_sync(0xFFFFFFFFu, k1[r], off);
            uint32_t mn = min(k0[r], o0);
            k0[r] = max(k0[r], o0);
            k1[r] = max(max(k1[r], o1), mn);
        }
        if (tig == 0) {
            int row = rbase + (r >> 1) * 16 + (r & 1) * 8 + g;
            sCand[row * 2 + 0] = 1023 - (int)(k0[r] & 1023u);
            sCand[row * 2 + 1] = 1023 - (int)(k1[r] & 1023u);
        }
    }
    __syncwarp();   // sCand rows are warp-private

    // ---- Cooperative exact fp32 rescore (dot-only vs g_wnorm) ----
    // unroll 2: rows are independent; lets row s+1's candidate LDGs fly
    // under row s's shuffle-reduce chains.
    const float NEGINF = -3.402823466e+38f;
    #pragma unroll 2
    for (int s = 0; s < 4; ++s) {
        const int row = rbase + g * 4 + s;
        const int sw  = row & 15;
        const int p0 = sCand[row * 2], p1 = sCand[row * 2 + 1];
        int cand[4] = {2 * p0, 2 * p0 + 1, 2 * p1, 2 * p1 + 1};
        float4 xq[4];
        #pragma unroll
        for (int j = 0; j < 4; ++j)
            xq[j] = *(const float4*)(sX + row * 64 + (((tig * 4 + j) ^ sw) << 2));
        float best = NEGINF;
        int   bi   = KK;
        #pragma unroll
        for (int c = 0; c < 4; ++c) {
            const int idx = cand[c];
            const float4* wp = (const float4*)(g_wnorm + (size_t)idx * DD) + tig * 4;
            float dot = 0.0f;
            #pragma unroll
            for (int j = 0; j < 4; ++j) {
                float4 v = wp[j];
                dot += v.x * xq[j].x + v.y * xq[j].y + v.z * xq[j].z + v.w * xq[j].w;
            }
            dot += __shfl_xor_sync(0xFFFFFFFFu, dot, 1);
            dot += __shfl_xor_sync(0xFFFFFFFFu, dot, 2);
            if (dot > best || (dot == best && idx < bi)) { best = dot; bi = idx; }
        }
        // overwrite this row of sX with the (already normalized) winner
        {
            const float4* wp = (const float4*)(g_wnorm + (size_t)bi * DD) + tig * 4;
            #pragma unroll
            for (int j = 0; j < 4; ++j)
                *(float4*)(sX + row * 64 + (((tig * 4 + j) ^ sw) << 2)) = wp[j];
        }
        if (tig == 0) {
            sCand[row * 2] = bi;
            sRED[row] = 2.0f - 2.0f * best;   // ||q - x||^2 for unit vectors
        }
    }
    __syncwarp();   // sX winner rows + sCand/sRED are warp-private

    // ---- Winner phase: stream own smem row (now q) to gmem, coalesced ----
    {
        int n = blockIdx.x * TILE_M + tid;
        int b = n >> 11;
        int t = n & (TT - 1);
        const int sw = tid & 15;
        float* qp = out + 1 + (size_t)b * DD * TT + t;
        #pragma unroll
        for (int i = 0; i < 16; ++i) {
            float4 q = *(const float4*)(sX + tid * 64 + ((i ^ sw) << 2));
            qp[(size_t)(i * 4 + 0) * TT] = q.x;
            qp[(size_t)(i * 4 + 1) * TT] = q.y;
            qp[(size_t)(i * 4 + 2) * TT] = q.z;
            qp[(size_t)(i * 4 + 3) * TT] = q.w;
        }
        out[1 + QELEMS + n] = (float)sCand[tid * 2];
    }

    // ---- Block loss reduce: warp shuffles + one cross-warp step ----
    {
        float v = sRED[tid];
        #pragma unroll
        for (int o = 16; o; o >>= 1) v += __shfl_xor_sync(0xFFFFFFFFu, v, o);
        if (lane == 0) sRED[256 + wid] = v;
    }
    __syncthreads();
    if (wid == 0) {
        float v = (lane < 8) ? sRED[256 + lane] : 0.0f;
        #pragma unroll
        for (int o = 4; o; o >>= 1) v += __shfl_xor_sync(0xFFFFFFFFu, v, o);
        if (lane == 0) g_partial[blockIdx.x] = v;
    }

    // ---- Deterministic last-block loss finalize ----
    if (tid == 0) {
        __threadfence();
        int old = atomicAdd(&g_ctr, 1);
        sLast = (old == GRID_M - 1) ? 1 : 0;
    }
    __syncthreads();
    if (sLast) {
        float v = g_partial[tid];
        #pragma unroll
        for (int o = 16; o; o >>= 1) v += __shfl_xor_sync(0xFFFFFFFFu, v, o);
        if (lane == 0) sRED[256 + wid] = v;
        __syncthreads();
        if (tid == 0) {
            float s = 0.0f;
            #pragma unroll
            for (int i = 0; i < 8; ++i) s += sRED[256 + i];
            out[0] = 1.25f * s / (float)QELEMS;   // q_loss + 0.25*e_loss (equal in value)
            out[out_size - 1] = 0.0f;             // n_resurrected
            g_ctr = 0;                            // reset for next graph replay
        }
    }
}

// ---------------------------------------------------------------------------
extern "C" void kernel_launch(void* const* d_in, const int* in_sizes, int n_in,
                              void* d_out, int out_size) {
    const float* in = (const float*)d_in[0];   // [B, D, T] float32
    const float* w  = (const float*)d_in[1];   // [K, D]    float32
    float* out = (float*)d_out;

    cudaFuncSetAttribute(vq_all_kernel, cudaFuncAttributeMaxDynamicSharedMemorySize, SM_TOTAL);

    norm_weight_kernel<<<16, 256>>>(w);
    vq_all_kernel<<<GRID_M, 256, SM_TOTAL>>>(in, out, out_size);
}